// round 1
// baseline (speedup 1.0000x reference)
#include <cuda_runtime.h>
#include <cuda_bf16.h>
#include <cstdint>

// CartesianToDihedral: inputs (1024, 2048, 3, 3) fp32 -> reshape (B=1024, N=6144 pts, 3)
// M = N-3 = 6141 dihedrals per row.
// out = [ sin(dih) (B,M) | cos(dih) (B,M) ] per row (axis -1 concat), then first_three (B,9).

#define TPB 256
#define N_PTS 6144
#define ROW_FLOATS (N_PTS * 3)          // 18432
#define M_DIH (N_PTS - 3)               // 6141
#define HALO_FLOATS ((TPB + 3) * 3)     // 777

__global__ __launch_bounds__(TPB) void cart2dih_kernel(
    const float* __restrict__ in,       // (B, N_PTS, 3)
    float* __restrict__ out_ang,        // (B, 2*M_DIH)
    float* __restrict__ out_first)      // (B, 9)
{
    __shared__ float s[HALO_FLOATS];

    const int tile = blockIdx.x;        // tile of dihedrals within a row
    const int b    = blockIdx.y;        // batch row
    const int base_pt = tile * TPB;     // first dihedral index in this tile
    const int base_f  = base_pt * 3;

    const float* __restrict__ row = in + (size_t)b * ROW_FLOATS;

    // Stage tile + 3-point halo into shared memory (coalesced).
    #pragma unroll
    for (int j = threadIdx.x; j < HALO_FLOATS; j += TPB) {
        int g = base_f + j;
        s[j] = (g < ROW_FLOATS) ? row[g] : 0.0f;
    }
    __syncthreads();

    const int i = base_pt + threadIdx.x;   // dihedral index
    if (i < M_DIH) {
        const float* p = s + threadIdx.x * 3;   // stride-3: bank-conflict-free (gcd(3,32)=1)
        float ax = p[0],  ay = p[1],  az = p[2];
        float bx = p[3],  by = p[4],  bz = p[5];
        float cx = p[6],  cy = p[7],  cz = p[8];
        float dx = p[9],  dy = p[10], dz = p[11];

        // bc_raw = b - c + 1e-8 (per component), normalized with norm clipped at 1e-12
        float ux = bx - cx + 1e-8f;
        float uy = by - cy + 1e-8f;
        float uz = bz - cz + 1e-8f;
        float nrm = sqrtf(ux*ux + uy*uy + uz*uz);
        float inv = 1.0f / fmaxf(nrm, 1e-12f);
        ux *= inv; uy *= inv; uz *= inv;

        // v = a - b ; w = c - d
        float vx = ax - bx, vy = ay - by, vz = az - bz;
        float wx = cx - dx, wy = cy - dy, wz = cz - dz;

        // n1 = cross(v, u)
        float n1x = vy*uz - vz*uy;
        float n1y = vz*ux - vx*uz;
        float n1z = vx*uy - vy*ux;
        // n2 = cross(u, w)
        float n2x = uy*wz - uz*wy;
        float n2y = uz*wx - ux*wz;
        float n2z = ux*wy - uy*wx;

        // xc = dot(n1, n2)
        float xc = n1x*n2x + n1y*n2y + n1z*n2z;
        // m = cross(n1, u);  yc = dot(m, n2)
        float mx = n1y*uz - n1z*uy;
        float my = n1z*ux - n1x*uz;
        float mz = n1x*uy - n1y*ux;
        float yc = mx*n2x + my*n2y + mz*n2z;

        // sin/cos of atan2(yc, xc+eps) == (yc, xc+eps)/r  (identical mathematically)
        float xp = xc + 1e-8f;
        float r2 = yc*yc + xp*xp;
        float sv, cv;
        if (r2 > 0.0f) {
            float rinv = rsqrtf(r2);
            sv = yc * rinv;
            cv = xp * rinv;
        } else {
            sv = 0.0f;      // atan2(0,0) = 0 -> sin 0, cos 1
            cv = 1.0f;
        }

        float* orow = out_ang + (size_t)b * (2 * M_DIH);
        orow[i]         = sv;
        orow[M_DIH + i] = cv;
    }

    // first_three: x[b, 0:3, :] -> 9 floats, handled once per row by tile 0
    if (tile == 0 && threadIdx.x < 9) {
        out_first[b * 9 + threadIdx.x] = row[threadIdx.x];
    }
}

extern "C" void kernel_launch(void* const* d_in, const int* in_sizes, int n_in,
                              void* d_out, int out_size)
{
    const float* in = (const float*)d_in[0];
    const int B = in_sizes[0] / ROW_FLOATS;     // 1024

    float* out_ang   = (float*)d_out;
    float* out_first = out_ang + (size_t)B * (2 * M_DIH);

    dim3 grid((M_DIH + TPB - 1) / TPB, B);
    cart2dih_kernel<<<grid, TPB>>>(in, out_ang, out_first);
}

// round 7
// speedup vs baseline: 1.2356x; 1.2356x over previous
#include <cuda_runtime.h>
#include <cuda_bf16.h>
#include <cstdint>

// CartesianToDihedral: inputs (1024, 2048, 3, 3) fp32 -> (B=1024, N=6144 pts, 3)
// M = 6141 dihedrals/row. out = [sin (B,M) | cos (B,M)] rows, then first_three (B,9).

#define TPB 256
#define DPT 4
#define TILE (TPB * DPT)                 // 1024 dihedrals per block
#define N_PTS 6144
#define ROW_FLOATS (N_PTS * 3)           // 18432
#define ROW_F4 (ROW_FLOATS / 4)          // 4608
#define M_DIH (N_PTS - 3)                // 6141
#define HALO_FLOATS ((TILE + 3) * 3)     // 3081
#define SMEM_F4 ((HALO_FLOATS + 3) / 4)  // 771 float4 = 3084 floats

__device__ __forceinline__ void dihedral(
    float ax, float ay, float az,
    float bx, float by, float bz,
    float cx, float cy, float cz,
    float dx, float dy, float dz,
    float& sv, float& cv)
{
    // u = normalize(b - c + 1e-8), norm clipped at 1e-12
    float ux = bx - cx + 1e-8f;
    float uy = by - cy + 1e-8f;
    float uz = bz - cz + 1e-8f;
    float nrm = sqrtf(fmaf(ux, ux, fmaf(uy, uy, uz * uz)));
    float inv = 1.0f / fmaxf(nrm, 1e-12f);
    ux *= inv; uy *= inv; uz *= inv;

    float vx = ax - bx, vy = ay - by, vz = az - bz;   // a - b
    float wx = cx - dx, wy = cy - dy, wz = cz - dz;   // c - d

    // n1 = cross(v, u); n2 = cross(u, w)
    float n1x = vy*uz - vz*uy;
    float n1y = vz*ux - vx*uz;
    float n1z = vx*uy - vy*ux;
    float n2x = uy*wz - uz*wy;
    float n2y = uz*wx - ux*wz;
    float n2z = ux*wy - uy*wx;

    float xc = n1x*n2x + n1y*n2y + n1z*n2z;
    // m = cross(n1, u); yc = dot(m, n2)
    float mx = n1y*uz - n1z*uy;
    float my = n1z*ux - n1x*uz;
    float mz = n1x*uy - n1y*ux;
    float yc = mx*n2x + my*n2y + mz*n2z;

    // sin/cos of atan2(yc, xc+eps) == (yc, xp)/r
    float xp = xc + 1e-8f;
    float r2 = fmaf(yc, yc, xp * xp);
    if (r2 > 0.0f) {
        float rinv = rsqrtf(r2);
        sv = yc * rinv;
        cv = xp * rinv;
    } else {
        sv = 0.0f;
        cv = 1.0f;
    }
}

__global__ __launch_bounds__(TPB) void cart2dih_kernel(
    const float* __restrict__ in,        // (B, N_PTS, 3)
    float* __restrict__ out_ang,         // (B, 2*M_DIH)
    float* __restrict__ out_first)       // (B, 9)
{
    __shared__ float4 s4[SMEM_F4];

    const int tile = blockIdx.x;
    const int b    = blockIdx.y;
    const int base = tile * TILE;                // first dihedral of tile
    const int base_f4 = tile * (TILE * 3 / 4);   // tile*768 float4, 16B-aligned

    const float4* __restrict__ rowv =
        (const float4*)(in + (size_t)b * ROW_FLOATS);   // row stride 18432 ≡ 0 mod 4 -> 16B OK

    // Stage tile + 3-point halo into shared memory, vectorized (LDG.128).
    #pragma unroll
    for (int j = threadIdx.x; j < SMEM_F4; j += TPB) {
        int g = base_f4 + j;
        s4[j] = (g < ROW_F4) ? rowv[g] : make_float4(0.f, 0.f, 0.f, 0.f);
    }
    __syncthreads();

    const int t  = threadIdx.x;
    const int i0 = base + t * DPT;               // first dihedral of this thread

    // 6x LDS.128: 8 points = 24 floats covering 4 consecutive dihedrals.
    // Stride 48B/thread: per 8-thread phase start-banks {0,12,24,4,16,28,8,20}
    // tile all 32 banks -> conflict-free.
    float4 A = s4[3*t + 0];
    float4 B = s4[3*t + 1];
    float4 C = s4[3*t + 2];
    float4 D = s4[3*t + 3];
    float4 E = s4[3*t + 4];
    float4 F = s4[3*t + 5];

    // points P0..P7, Pk = floats [3k, 3k+3) of {A,B,C,D,E,F}
    float sv[DPT], cv[DPT];
    //        a: P(k)          b: P(k+1)        c: P(k+2)        d: P(k+3)
    dihedral(A.x, A.y, A.z,   A.w, B.x, B.y,   B.z, B.w, C.x,   C.y, C.z, C.w, sv[0], cv[0]);
    dihedral(A.w, B.x, B.y,   B.z, B.w, C.x,   C.y, C.z, C.w,   D.x, D.y, D.z, sv[1], cv[1]);
    dihedral(B.z, B.w, C.x,   C.y, C.z, C.w,   D.x, D.y, D.z,   D.w, E.x, E.y, sv[2], cv[2]);
    dihedral(C.y, C.z, C.w,   D.x, D.y, D.z,   D.w, E.x, E.y,   E.z, E.w, F.x, sv[3], cv[3]);

    float* __restrict__ orow = out_ang + (size_t)b * (2 * M_DIH);

    if (i0 + DPT - 1 < M_DIH) {
        // sin half: row base offset b*12282 ≡ 2 (mod 4) for odd b -> only 8B
        // alignment guaranteed: two STG.64, never STG.128.
        *(float2*)(orow + i0)     = make_float2(sv[0], sv[1]);
        *(float2*)(orow + i0 + 2) = make_float2(sv[2], sv[3]);
        // cos half: offsets odd-parity -> 4B aligned, scalar stores
        orow[M_DIH + i0 + 0] = cv[0];
        orow[M_DIH + i0 + 1] = cv[1];
        orow[M_DIH + i0 + 2] = cv[2];
        orow[M_DIH + i0 + 3] = cv[3];
    } else {
        #pragma unroll
        for (int k = 0; k < DPT; k++) {
            int i = i0 + k;
            if (i < M_DIH) {
                orow[i]         = sv[k];
                orow[M_DIH + i] = cv[k];
            }
        }
    }

    // first_three: 9 floats per row, handled by tile 0
    if (tile == 0 && t < 9)
        out_first[b * 9 + t] = in[(size_t)b * ROW_FLOATS + t];
}

extern "C" void kernel_launch(void* const* d_in, const int* in_sizes, int n_in,
                              void* d_out, int out_size)
{
    const float* in = (const float*)d_in[0];
    const int B = in_sizes[0] / ROW_FLOATS;      // 1024

    float* out_ang   = (float*)d_out;
    float* out_first = out_ang + (size_t)B * (2 * M_DIH);

    dim3 grid((M_DIH + TILE - 1) / TILE, B);     // (6, 1024)
    cart2dih_kernel<<<grid, TPB>>>(in, out_ang, out_first);
}

// round 10
// speedup vs baseline: 1.3699x; 1.1087x over previous
#include <cuda_runtime.h>
#include <cuda_bf16.h>
#include <cstdint>

// CartesianToDihedral: inputs (1024, 2048, 3, 3) fp32 -> (B=1024, N=6144 pts, 3)
// M = 6141 dihedrals/row. out = [sin (B,M) | cos (B,M)] rows, then first_three (B,9).

#define TPB 256
#define DPT 4
#define TILE (TPB * DPT)                 // 1024 dihedrals per block
#define N_PTS 6144
#define ROW_FLOATS (N_PTS * 3)           // 18432
#define ROW_F4 (ROW_FLOATS / 4)          // 4608
#define M_DIH (N_PTS - 3)                // 6141
#define HALO_FLOATS ((TILE + 3) * 3)     // 3081
#define SMEM_F4 ((HALO_FLOATS + 3) / 4)  // 771 float4 = 3084 floats

__device__ __forceinline__ void dihedral(
    float ax, float ay, float az,
    float bx, float by, float bz,
    float cx, float cy, float cz,
    float dx, float dy, float dz,
    float& sv, float& cv)
{
    // u = normalize(b - c + 1e-8), norm clipped at 1e-12.
    // 1/max(sqrt(r2),1e-12) == rsqrt(max(r2,1e-24)): single MUFU.RSQ instead of
    // IEEE sqrt-sequence + IEEE div-sequence (~20+ instrs saved per dihedral).
    float ux = bx - cx + 1e-8f;
    float uy = by - cy + 1e-8f;
    float uz = bz - cz + 1e-8f;
    float r2u = fmaf(ux, ux, fmaf(uy, uy, uz * uz));
    float inv = rsqrtf(fmaxf(r2u, 1e-24f));
    ux *= inv; uy *= inv; uz *= inv;

    float vx = ax - bx, vy = ay - by, vz = az - bz;   // a - b
    float wx = cx - dx, wy = cy - dy, wz = cz - dz;   // c - d

    // n1 = cross(v, u); n2 = cross(u, w)
    float n1x = vy*uz - vz*uy;
    float n1y = vz*ux - vx*uz;
    float n1z = vx*uy - vy*ux;
    float n2x = uy*wz - uz*wy;
    float n2y = uz*wx - ux*wz;
    float n2z = ux*wy - uy*wx;

    float xc = n1x*n2x + n1y*n2y + n1z*n2z;
    // m = cross(n1, u); yc = dot(m, n2)
    float mx = n1y*uz - n1z*uy;
    float my = n1z*ux - n1x*uz;
    float mz = n1x*uy - n1y*ux;
    float yc = mx*n2x + my*n2y + mz*n2z;

    // sin/cos of atan2(yc, xc+eps) == (yc, xp)/r
    float xp = xc + 1e-8f;
    float r2 = fmaf(yc, yc, xp * xp);
    if (r2 > 0.0f) {
        float rinv = rsqrtf(r2);
        sv = yc * rinv;
        cv = xp * rinv;
    } else {
        sv = 0.0f;
        cv = 1.0f;
    }
}

__global__ __launch_bounds__(TPB) void cart2dih_kernel(
    const float* __restrict__ in,        // (B, N_PTS, 3)
    float* __restrict__ out_ang,         // (B, 2*M_DIH)
    float* __restrict__ out_first)       // (B, 9)
{
    __shared__ float4 s4[SMEM_F4];

    const int tile = blockIdx.x;
    const int b    = blockIdx.y;
    const int base = tile * TILE;                // first dihedral of tile
    const int base_f4 = tile * (TILE * 3 / 4);   // tile*768 float4, 16B-aligned

    const float4* __restrict__ rowv =
        (const float4*)(in + (size_t)b * ROW_FLOATS);   // row stride 18432 ≡ 0 mod 4 -> 16B OK

    // Stage tile + 3-point halo into shared memory, vectorized (LDG.128).
    #pragma unroll
    for (int j = threadIdx.x; j < SMEM_F4; j += TPB) {
        int g = base_f4 + j;
        s4[j] = (g < ROW_F4) ? rowv[g] : make_float4(0.f, 0.f, 0.f, 0.f);
    }
    __syncthreads();

    const int t  = threadIdx.x;
    const int i0 = base + t * DPT;               // first dihedral of this thread

    // 6x LDS.128: 8 points = 24 floats covering 4 consecutive dihedrals.
    // Stride 48B/thread: per 8-thread phase start-banks {0,12,24,4,16,28,8,20}
    // tile all 32 banks -> conflict-free.
    float4 A = s4[3*t + 0];
    float4 B = s4[3*t + 1];
    float4 C = s4[3*t + 2];
    float4 D = s4[3*t + 3];
    float4 E = s4[3*t + 4];
    float4 F = s4[3*t + 5];

    // points P0..P7, Pk = floats [3k, 3k+3) of {A,B,C,D,E,F}
    float sv[DPT], cv[DPT];
    //        a: P(k)          b: P(k+1)        c: P(k+2)        d: P(k+3)
    dihedral(A.x, A.y, A.z,   A.w, B.x, B.y,   B.z, B.w, C.x,   C.y, C.z, C.w, sv[0], cv[0]);
    dihedral(A.w, B.x, B.y,   B.z, B.w, C.x,   C.y, C.z, C.w,   D.x, D.y, D.z, sv[1], cv[1]);
    dihedral(B.z, B.w, C.x,   C.y, C.z, C.w,   D.x, D.y, D.z,   D.w, E.x, E.y, sv[2], cv[2]);
    dihedral(C.y, C.z, C.w,   D.x, D.y, D.z,   D.w, E.x, E.y,   E.z, E.w, F.x, sv[3], cv[3]);

    float* __restrict__ orow = out_ang + (size_t)b * (2 * M_DIH);

    if (i0 + DPT - 1 < M_DIH) {
        // sin half: row base offset b*12282 ≡ 2 (mod 4) for odd b -> only 8B
        // alignment guaranteed: two STG.64, never STG.128.
        *(float2*)(orow + i0)     = make_float2(sv[0], sv[1]);
        *(float2*)(orow + i0 + 2) = make_float2(sv[2], sv[3]);
        // cos half: offsets odd-parity -> 4B aligned, scalar stores
        orow[M_DIH + i0 + 0] = cv[0];
        orow[M_DIH + i0 + 1] = cv[1];
        orow[M_DIH + i0 + 2] = cv[2];
        orow[M_DIH + i0 + 3] = cv[3];
    } else {
        #pragma unroll
        for (int k = 0; k < DPT; k++) {
            int i = i0 + k;
            if (i < M_DIH) {
                orow[i]         = sv[k];
                orow[M_DIH + i] = cv[k];
            }
        }
    }

    // first_three: 9 floats per row, handled by tile 0
    if (tile == 0 && t < 9)
        out_first[b * 9 + t] = in[(size_t)b * ROW_FLOATS + t];
}

extern "C" void kernel_launch(void* const* d_in, const int* in_sizes, int n_in,
                              void* d_out, int out_size)
{
    const float* in = (const float*)d_in[0];
    const int B = in_sizes[0] / ROW_FLOATS;      // 1024

    float* out_ang   = (float*)d_out;
    float* out_first = out_ang + (size_t)B * (2 * M_DIH);

    dim3 grid((M_DIH + TILE - 1) / TILE, B);     // (6, 1024)
    cart2dih_kernel<<<grid, TPB>>>(in, out_ang, out_first);
}